// round 8
// baseline (speedup 1.0000x reference)
#include <cuda_runtime.h>
#include <stdint.h>
#include <math.h>

#define JAX_PARTITIONABLE 1

#define NROWS   65536
#define TSTEPS  12
#define WPB     8
#define THREADS 256
#define NBLOCKS 296        // 2 CTAs/SM on 148 SMs

// output layout (float32): seq | ent | logp | cnt | lengths | mask
#define OFF_ENT  (NROWS * TSTEPS)
#define OFF_LP   (2 * NROWS * TSTEPS)
#define OFF_CNT  (3 * NROWS * TSTEPS)
#define OFF_LEN  (OFF_CNT + NROWS)
#define OFF_MASK (OFF_LEN + NROWS)

// shared layout (float slots)
#define SM_WH    0          // 128x128 = 16384
#define SM_WP    16384      // 128x16 (original layout) = 2048
#define SM_B     18432      // 128
#define SM_BP    18560      // 16
#define SM_H0    18576      // 128
#define SM_KEY   18704      // 24 u32
#define SM_HS    18728      // 8 warps * 4 pairs * 128 f32x2 = 8192 floats (16B aligned)
#define SM_SEQ   26920      // 8 warps * 8 * 12 int = 768
#define SM_ST    27688      // 8 warps * 8 * 8  int = 512
#define SM_TOTF  28200      // 112800 bytes -> 2 CTAs/SM fit

typedef unsigned long long u64t;

__device__ __forceinline__ u64t pk2(float lo, float hi) {
    u64t r;
    asm("mov.b64 %0, {%1, %2};" : "=l"(r) : "f"(lo), "f"(hi));
    return r;
}
__device__ __forceinline__ u64t pkdup(float v) { return pk2(v, v); }
__device__ __forceinline__ void upk2(u64t x, float& lo, float& hi) {
    asm("mov.b64 {%0, %1}, %2;" : "=f"(lo), "=f"(hi) : "l"(x));
}
__device__ __forceinline__ u64t fma2(u64t a, u64t b, u64t c) {
    u64t d;
    asm("fma.rn.f32x2 %0, %1, %2, %3;" : "=l"(d) : "l"(a), "l"(b), "l"(c));
    return d;
}

__device__ __forceinline__ uint32_t rotl32(uint32_t x, int n) {
    return (x << n) | (x >> (32 - n));
}

// Threefry-2x32, 20 rounds (exact JAX cipher)
__device__ __forceinline__ void tf2x32(uint32_t k0, uint32_t k1,
                                       uint32_t &x0, uint32_t &x1) {
    uint32_t k2 = k0 ^ k1 ^ 0x1BD11BDAu;
    x0 += k0; x1 += k1;
#define TFR(r) { x0 += x1; x1 = rotl32(x1, (r)); x1 ^= x0; }
    TFR(13) TFR(15) TFR(26) TFR(6)
    x0 += k1; x1 += k2 + 1u;
    TFR(17) TFR(29) TFR(16) TFR(24)
    x0 += k2; x1 += k0 + 2u;
    TFR(13) TFR(15) TFR(26) TFR(6)
    x0 += k0; x1 += k1 + 3u;
    TFR(17) TFR(29) TFR(16) TFR(24)
    x0 += k1; x1 += k2 + 4u;
    TFR(13) TFR(15) TFR(26) TFR(6)
    x0 += k2; x1 += k0 + 5u;
#undef TFR
}

__device__ __forceinline__ uint32_t gbits(uint32_t k0, uint32_t k1, uint32_t idx) {
#if JAX_PARTITIONABLE
    uint32_t a = 0u, b = idx;
    tf2x32(k0, k1, a, b);
    return a ^ b;
#else
    const uint32_t half = (uint32_t)(NROWS * 16) / 2u;
    if (idx < half) {
        uint32_t a = idx, b = idx + half;
        tf2x32(k0, k1, a, b);
        return a;
    } else {
        uint32_t a = idx - half, b = idx;
        tf2x32(k0, k1, a, b);
        return b;
    }
#endif
}

// One group of R rows (R even). h pair-interleaved in smem:
// hw[pair*128 + k] = (h_{2p}[k], h_{2p+1}[k]) packed f32x2.
// Sampler geometry: lane = rr*4 + q ; rr = row (0..7), q = token quartet (tokens 4q..4q+3).
template <int R>
__device__ __forceinline__ void run_group(
    int rowBase, float* __restrict__ sm, u64t* __restrict__ hw,
    int* __restrict__ seqw, int* __restrict__ stw,
    const float4* __restrict__ Wx4, float* __restrict__ out,
    int lane,
    const u64t* __restrict__ ivd,
    float4 bvecv, u64t hinit0, u64t hinit1, u64t hinit2, u64t hinit3,
    float4 bpq)
{
    constexpr int NP = R / 2;
    const float NEG_INF = __int_as_float(0xff800000);
    const uint32_t* keys = (const uint32_t*)(sm + SM_KEY);

    const int rr   = lane >> 2;      // sampler row
    const int q    = lane & 3;       // token quartet
    const int spair = rr >> 1;
    const int shalf = rr & 1;

    // ---- init group ----
#pragma unroll
    for (int p = 0; p < NP; p++) {
        u64t* pw = hw + p * 128 + lane * 4;
        pw[0] = hinit0; pw[1] = hinit1; pw[2] = hinit2; pw[3] = hinit3;
    }
    if (lane < R) {
        int* st = stw + lane * 8;
        st[0] = 1; st[1] = 0; st[2] = 1; st[3] = 0; st[4] = 1; st[5] = -1; st[6] = -1;
        out[OFF_MASK + (size_t)(rowBase + lane) * 13] = 1.0f;
    }
    __syncwarp();

    for (int t = 0; t < TSTEPS; t++) {
        const uint32_t k0 = keys[2 * t];
        const uint32_t k1 = keys[2 * t + 1];

        // ---- acc2 init = pack(x@Wx + b) per pair ----
        u64t acc2[NP][4];
        if (t == 0) {
#pragma unroll
            for (int p = 0; p < NP; p++) {
                acc2[p][0] = ivd[0]; acc2[p][1] = ivd[1];
                acc2[p][2] = ivd[2]; acc2[p][3] = ivd[3];
            }
        } else {
#pragma unroll
            for (int p = 0; p < NP; p++) {
                int p0a = stw[(2 * p) * 8 + 5],     p1a = stw[(2 * p) * 8 + 6];
                int p0b = stw[(2 * p + 1) * 8 + 5], p1b = stw[(2 * p + 1) * 8 + 6];
                float4 a0 = make_float4(0.f, 0.f, 0.f, 0.f), c0 = a0, a1 = a0, c1 = a0;
                if (p0a >= 0) a0 = __ldg(Wx4 + p0a * 32 + lane);
                if (p1a >= 0) c0 = __ldg(Wx4 + (16 + p1a) * 32 + lane);
                if (p0b >= 0) a1 = __ldg(Wx4 + p0b * 32 + lane);
                if (p1b >= 0) c1 = __ldg(Wx4 + (16 + p1b) * 32 + lane);
                acc2[p][0] = pk2(a0.x + c0.x + bvecv.x, a1.x + c1.x + bvecv.x);
                acc2[p][1] = pk2(a0.y + c0.y + bvecv.y, a1.y + c1.y + bvecv.y);
                acc2[p][2] = pk2(a0.z + c0.z + bvecv.z, a1.z + c1.z + bvecv.z);
                acc2[p][3] = pk2(a0.w + c0.w + bvecv.w, a1.w + c1.w + bvecv.w);
            }
        }

        // ---- h @ Wh with packed FFMA2 ----
        {
            const float4* Wh4 = (const float4*)sm;  // SM_WH == 0
#pragma unroll 1
            for (int k4 = 0; k4 < 32; k4++) {
                u64t hk[NP][4];
#pragma unroll
                for (int p = 0; p < NP; p++) {
                    const u64t* ph = hw + p * 128 + 4 * k4;
                    hk[p][0] = ph[0]; hk[p][1] = ph[1];
                    hk[p][2] = ph[2]; hk[p][3] = ph[3];
                }
#pragma unroll
                for (int kk = 0; kk < 4; kk++) {
                    float4 w = Wh4[(k4 * 4 + kk) * 32 + lane];
                    u64t wd0 = pkdup(w.x), wd1 = pkdup(w.y);
                    u64t wd2 = pkdup(w.z), wd3 = pkdup(w.w);
#pragma unroll
                    for (int p = 0; p < NP; p++) {
                        acc2[p][0] = fma2(hk[p][kk], wd0, acc2[p][0]);
                        acc2[p][1] = fma2(hk[p][kk], wd1, acc2[p][1]);
                        acc2[p][2] = fma2(hk[p][kk], wd2, acc2[p][2]);
                        acc2[p][3] = fma2(hk[p][kk], wd3, acc2[p][3]);
                    }
                }
            }
            __syncwarp();
#pragma unroll
            for (int p = 0; p < NP; p++) {
                u64t* pw = hw + p * 128 + lane * 4;
#pragma unroll
                for (int v = 0; v < 4; v++) {
                    float lo, hi;
                    upk2(acc2[p][v], lo, hi);
                    pw[v] = pk2(tanhf(lo), tanhf(hi));
                }
            }
            __syncwarp();
        }

        // ---- logits: lane computes tokens 4q..4q+3 for row rr ----
        float lg[4];
        {
            u64t a01 = 0ull, a23 = 0ull;
            const u64t* ph = hw + spair * 128;
            const u64t* Wp64 = (const u64t*)(sm + SM_WP);
#pragma unroll 4
            for (int k4 = 0; k4 < 32; k4++) {
                ulonglong2 hA = *(const ulonglong2*)(ph + 4 * k4);
                ulonglong2 hB = *(const ulonglong2*)(ph + 4 * k4 + 2);
                float h0l, h0h, h1l, h1h, h2l, h2h, h3l, h3h;
                upk2(hA.x, h0l, h0h); upk2(hA.y, h1l, h1h);
                upk2(hB.x, h2l, h2h); upk2(hB.y, h3l, h3h);
                float hv0 = shalf ? h0h : h0l;
                float hv1 = shalf ? h1h : h1l;
                float hv2 = shalf ? h2h : h2l;
                float hv3 = shalf ? h3h : h3l;
                ulonglong2 w0 = *(const ulonglong2*)(Wp64 + (4 * k4 + 0) * 8 + q * 2);
                ulonglong2 w1 = *(const ulonglong2*)(Wp64 + (4 * k4 + 1) * 8 + q * 2);
                ulonglong2 w2 = *(const ulonglong2*)(Wp64 + (4 * k4 + 2) * 8 + q * 2);
                ulonglong2 w3 = *(const ulonglong2*)(Wp64 + (4 * k4 + 3) * 8 + q * 2);
                u64t hd0 = pkdup(hv0), hd1 = pkdup(hv1);
                u64t hd2 = pkdup(hv2), hd3 = pkdup(hv3);
                a01 = fma2(hd0, w0.x, a01); a23 = fma2(hd0, w0.y, a23);
                a01 = fma2(hd1, w1.x, a01); a23 = fma2(hd1, w1.y, a23);
                a01 = fma2(hd2, w2.x, a01); a23 = fma2(hd2, w2.y, a23);
                a01 = fma2(hd3, w3.x, a01); a23 = fma2(hd3, w3.y, a23);
            }
            float l0, l1, l2, l3;
            upk2(a01, l0, l1); upk2(a23, l2, l3);
            lg[0] = l0 + bpq.x; lg[1] = l1 + bpq.y;
            lg[2] = l2 + bpq.z; lg[3] = l3 + bpq.w;
        }

        // ---- constraints (PRE-update state of row rr) ----
        int cnt = stw[rr * 8 + 0], ln = stw[rr * 8 + 1], hv = stw[rr * 8 + 3];
        int cl = cnt + ln;
        bool ok[4];
        if (q < 2) {
            bool o = !(cl > TSTEPS - 2);   // tokens 0..7
            ok[0] = o; ok[1] = o; ok[2] = o; ok[3] = o;
        } else {
            bool o = !(cl < 2);            // tokens 8..15
            ok[0] = o; ok[1] = o; ok[2] = o; ok[3] = o;
            if (q == 2 && cnt == 1 && hv == 0) ok[0] = false;  // token 8
        }

        // ---- max over 16 tokens: in-lane + 2 shfl rounds ----
        float m = fmaxf(fmaxf(lg[0], lg[1]), fmaxf(lg[2], lg[3]));
        m = fmaxf(m, __shfl_xor_sync(0xffffffffu, m, 1));
        m = fmaxf(m, __shfl_xor_sync(0xffffffffu, m, 2));

        // ---- exp + masked sum (z cancels algebraically) ----
        float ex[4];
#pragma unroll
        for (int j = 0; j < 4; j++) ex[j] = expf(lg[j] - m);
        float zm = (ok[0] ? ex[0] : 0.f) + (ok[1] ? ex[1] : 0.f)
                 + (ok[2] ? ex[2] : 0.f) + (ok[3] ? ex[3] : 0.f);
        zm += __shfl_xor_sync(0xffffffffu, zm, 1);
        zm += __shfl_xor_sync(0xffffffffu, zm, 2);

        float pz  = 1.0f / zm;
        float lzm = logf(zm);
        float p[4], logp[4];
#pragma unroll
        for (int j = 0; j < 4; j++) {
            p[j]    = ok[j] ? ex[j] * pz : 0.0f;
            logp[j] = ok[j] ? (lg[j] - m) - lzm : NEG_INF;
        }

        // ---- gumbel (exact threefry bits) + in-lane argmax ----
        float bsc = NEG_INF;
        int bj = 0;
#pragma unroll
        for (int j = 0; j < 4; j++) {
            uint32_t idx = ((uint32_t)(rowBase + rr)) * 16u + (uint32_t)(4 * q + j);
            uint32_t bts = gbits(k0, k1, idx);
            float f = __uint_as_float((bts >> 9) | 0x3f800000u) - 1.0f;
            float u = (f == 0.0f) ? 1.17549435e-38f : f;
            float gu = -logf(-logf(u));
            float sc = ok[j] ? (logp[j] + gu) : NEG_INF;
            if (sc > bsc) { bsc = sc; bj = j; }
        }
        int btok = 4 * q + bj;
        // cross-lane argmax (2 rounds), first-index tie-break
#pragma unroll
        for (int d = 1; d < 4; d <<= 1) {
            float os = __shfl_xor_sync(0xffffffffu, bsc, d);
            int   oi = __shfl_xor_sync(0xffffffffu, btok, d);
            if (os > bsc || (os == bsc && oi < btok)) { bsc = os; btok = oi; }
        }

        // ---- entropy: in-lane + 2 rounds ----
        float et = (ok[0] ? p[0] * logp[0] : 0.f) + (ok[1] ? p[1] * logp[1] : 0.f)
                 + (ok[2] ? p[2] * logp[2] : 0.f) + (ok[3] ? p[3] * logp[3] : 0.f);
        et += __shfl_xor_sync(0xffffffffu, et, 1);
        et += __shfl_xor_sync(0xffffffffu, et, 2);

        // ---- logp at chosen token: fetch from owner lane ----
        int jb = btok & 3;
        float cand = (jb == 0) ? logp[0] : (jb == 1) ? logp[1] : (jb == 2) ? logp[2] : logp[3];
        float lpv = __shfl_sync(0xffffffffu, cand, (lane & ~3) + (btok >> 2));

        // ---- writer lane per row (q==0): state, outputs, parent/sibling ----
        if (q == 0 && rr < R) {
            int tok = btok;
            int* st = stw + rr * 8;
            int row = rowBase + rr;

            seqw[rr * 12 + t] = tok;
            int ar   = (tok < 4) ? 2 : ((tok < 8) ? 1 : 0);
            int ncnt = st[0] - 1 + ar;
            int nln  = st[1] + 1;
            int act  = (ncnt > 0) && st[2];
            st[0] = ncnt; st[1] = nln; st[2] = act;
            st[3] = st[3] | (tok >= 9);
            st[4] += act;

            out[(size_t)row * 12 + t]                = (float)tok;
            out[OFF_ENT + (size_t)row * 12 + t]      = -et;
            out[OFF_LP  + (size_t)row * 12 + t]      = lpv;
            out[OFF_MASK + (size_t)row * 13 + 1 + t] = act ? 1.0f : 0.0f;

            // parent/sibling (reads only this row's seq, all written by this lane)
            int ps0, ps1;
            if (tok < 8) {
                ps0 = tok; ps1 = -1;
            } else {
                ps0 = -1; ps1 = -1;
                int c = 0;
                bool found = false;
                for (int i = t; i >= 0; i--) {
                    int tk2 = seqw[rr * 12 + i];
                    int a2 = (tk2 < 4) ? 2 : ((tk2 < 8) ? 1 : 0);
                    c += a2 - 1;
                    if (!found && c == 0) {
                        ps0 = tk2;
                        ps1 = (i + 1 < TSTEPS) ? seqw[rr * 12 + i + 1] : -1;
                        found = true;
                    }
                }
            }
            st[5] = ps0; st[6] = ps1;
        }
        __syncwarp();
    }

    // ---- finalize group ----
    if (lane < R) {
        out[OFF_CNT + rowBase + lane] = (float)stw[lane * 8 + 0];
        out[OFF_LEN + rowBase + lane] = (float)stw[lane * 8 + 4];
    }
    __syncwarp();
}

__global__ void __launch_bounds__(THREADS, 2)
eq_sampler(const float* __restrict__ in0, const float* __restrict__ h0,
           const float* __restrict__ Wx, const float* __restrict__ Wh,
           const float* __restrict__ b,  const float* __restrict__ Wp,
           const float* __restrict__ bp, float* __restrict__ out) {
    extern __shared__ float sm[];
    int* smi = (int*)sm;
    const int tid = threadIdx.x;

    for (int i = tid; i < 16384; i += THREADS) sm[SM_WH + i] = Wh[i];
    for (int i = tid; i < 2048;  i += THREADS) sm[SM_WP + i] = Wp[i];
    if (tid < 128) sm[SM_B  + tid] = b[tid];
    if (tid < 16)  sm[SM_BP + tid] = bp[tid];
    if (tid < 128) sm[SM_H0 + tid] = h0[tid];

    if (tid == 0) {
        uint32_t* kp = (uint32_t*)(sm + SM_KEY);
#if JAX_PARTITIONABLE
        for (int t = 0; t < TSTEPS; t++) {
            uint32_t a = 0u, bb = (uint32_t)t;
            tf2x32(0u, 42u, a, bb);
            kp[2 * t] = a; kp[2 * t + 1] = bb;
        }
#else
        uint32_t ov[24];
        for (int j = 0; j < 12; j++) {
            uint32_t a = (uint32_t)j, bb = (uint32_t)(j + 12);
            tf2x32(0u, 42u, a, bb);
            ov[j] = a; ov[12 + j] = bb;
        }
        for (int t = 0; t < TSTEPS; t++) { kp[2 * t] = ov[2 * t]; kp[2 * t + 1] = ov[2 * t + 1]; }
#endif
    }
    __syncthreads();

    const int wid  = tid >> 5;
    const int lane = tid & 31;

    u64t* hw  = (u64t*)(sm + SM_HS) + wid * 512;
    int* seqw = smi + SM_SEQ + wid * 96;
    int* stw  = smi + SM_ST  + wid * 64;

    // t=0 input projection (identical for all rows) from global
    float4 xw0v;
    {
        float s0 = 0.f, s1 = 0.f, s2 = 0.f, s3 = 0.f;
#pragma unroll
        for (int k = 0; k < 32; k++) {
            float iv = __ldg(in0 + k);
            const float* wr = Wx + k * 128 + lane * 4;
            s0 = fmaf(iv, __ldg(wr + 0), s0);
            s1 = fmaf(iv, __ldg(wr + 1), s1);
            s2 = fmaf(iv, __ldg(wr + 2), s2);
            s3 = fmaf(iv, __ldg(wr + 3), s3);
        }
        xw0v = make_float4(s0, s1, s2, s3);
    }
    const float4 bvecv = ((const float4*)(sm + SM_B))[lane];
    const float4 hinit = ((const float4*)(sm + SM_H0))[lane];
    const float4 bpq   = ((const float4*)(sm + SM_BP))[lane & 3];
    const float4* Wx4  = (const float4*)Wx;

    u64t ivd[4];
    ivd[0] = pkdup(xw0v.x + bvecv.x);
    ivd[1] = pkdup(xw0v.y + bvecv.y);
    ivd[2] = pkdup(xw0v.z + bvecv.z);
    ivd[3] = pkdup(xw0v.w + bvecv.w);
    const u64t hi0 = pkdup(hinit.x), hi1 = pkdup(hinit.y);
    const u64t hi2 = pkdup(hinit.z), hi3 = pkdup(hinit.w);

    const int totalWarps = gridDim.x * WPB;
    const int gwid = blockIdx.x * WPB + wid;

    const int full8 = NROWS / 8;
    const int base8 = (full8 / totalWarps) * totalWarps;
    for (int grp = gwid; grp < base8; grp += totalWarps)
        run_group<8>(grp * 8, sm, hw, seqw, stw, Wx4, out,
                     lane, ivd, bvecv, hi0, hi1, hi2, hi3, bpq);

    const int tailRowBase = base8 * 8;
    const int tail4 = (NROWS - tailRowBase) / 4;
    for (int grp = gwid; grp < tail4; grp += totalWarps)
        run_group<4>(tailRowBase + grp * 4, sm, hw, seqw, stw, Wx4, out,
                     lane, ivd, bvecv, hi0, hi1, hi2, hi3, bpq);
}

extern "C" void kernel_launch(void* const* d_in, const int* in_sizes, int n_in,
                              void* d_out, int out_size) {
    int base = (in_sizes[0] == 1) ? 1 : 0;
    const float* in0 = (const float*)d_in[base + 0];
    const float* h0  = (const float*)d_in[base + 1];
    const float* Wx  = (const float*)d_in[base + 2];
    const float* Wh  = (const float*)d_in[base + 3];
    const float* b   = (const float*)d_in[base + 4];
    const float* Wp  = (const float*)d_in[base + 5];
    const float* bp  = (const float*)d_in[base + 6];

    size_t smem = (size_t)SM_TOTF * sizeof(float);
    cudaFuncSetAttribute(eq_sampler, cudaFuncAttributeMaxDynamicSharedMemorySize, (int)smem);
    eq_sampler<<<NBLOCKS, THREADS, smem>>>(in0, h0, Wx, Wh, b, Wp, bp, (float*)d_out);
}

// round 9
// speedup vs baseline: 1.0167x; 1.0167x over previous
#include <cuda_runtime.h>
#include <stdint.h>
#include <math.h>

#define JAX_PARTITIONABLE 1

#define NROWS   65536
#define TSTEPS  12
#define WPB     8
#define THREADS 256
#define NBLOCKS 296        // 2 CTAs/SM on 148 SMs

// output layout (float32): seq | ent | logp | cnt | lengths | mask
#define OFF_ENT  (NROWS * TSTEPS)
#define OFF_LP   (2 * NROWS * TSTEPS)
#define OFF_CNT  (3 * NROWS * TSTEPS)
#define OFF_LEN  (OFF_CNT + NROWS)
#define OFF_MASK (OFF_LEN + NROWS)

// shared layout (float slots)
#define SM_WH    0          // 128x128 = 16384
#define SM_WPT   16384      // 16 x 132 (transposed Wp, padded) = 2112
#define SM_B     18496      // 128
#define SM_BP    18624      // 16
#define SM_H0    18640      // 128
#define SM_KEY   18768      // 24 u32
#define SM_HS    18792      // 8 warps * 4 pairs * 128 f32x2 = 8192 floats (16B aligned)
#define SM_SEQ   26984      // 8 warps * 8 * 12 int = 768
#define SM_ST    27752      // 8 warps * 8 * 8  int = 512
#define SM_TOTF  28264      // 113056 bytes -> 2 CTAs/SM fit

typedef unsigned long long u64t;

__device__ __forceinline__ u64t pk2(float lo, float hi) {
    u64t r;
    asm("mov.b64 %0, {%1, %2};" : "=l"(r) : "f"(lo), "f"(hi));
    return r;
}
__device__ __forceinline__ u64t pkdup(float v) { return pk2(v, v); }
__device__ __forceinline__ void upk2(u64t x, float& lo, float& hi) {
    asm("mov.b64 {%0, %1}, %2;" : "=f"(lo), "=f"(hi) : "l"(x));
}
// packed dual-fp32 FMA (Blackwell): lo/hi halves are independent fp32 FMAs
__device__ __forceinline__ u64t fma2(u64t a, u64t b, u64t c) {
    u64t d;
    asm("fma.rn.f32x2 %0, %1, %2, %3;" : "=l"(d) : "l"(a), "l"(b), "l"(c));
    return d;
}

__device__ __forceinline__ uint32_t rotl32(uint32_t x, int n) {
    return (x << n) | (x >> (32 - n));
}

// Threefry-2x32, 20 rounds (exact JAX cipher)
__device__ __forceinline__ void tf2x32(uint32_t k0, uint32_t k1,
                                       uint32_t &x0, uint32_t &x1) {
    uint32_t k2 = k0 ^ k1 ^ 0x1BD11BDAu;
    x0 += k0; x1 += k1;
#define TFR(r) { x0 += x1; x1 = rotl32(x1, (r)); x1 ^= x0; }
    TFR(13) TFR(15) TFR(26) TFR(6)
    x0 += k1; x1 += k2 + 1u;
    TFR(17) TFR(29) TFR(16) TFR(24)
    x0 += k2; x1 += k0 + 2u;
    TFR(13) TFR(15) TFR(26) TFR(6)
    x0 += k0; x1 += k1 + 3u;
    TFR(17) TFR(29) TFR(16) TFR(24)
    x0 += k1; x1 += k2 + 4u;
    TFR(13) TFR(15) TFR(26) TFR(6)
    x0 += k2; x1 += k0 + 5u;
#undef TFR
}

__device__ __forceinline__ uint32_t gbits(uint32_t k0, uint32_t k1, uint32_t idx) {
#if JAX_PARTITIONABLE
    uint32_t a = 0u, b = idx;
    tf2x32(k0, k1, a, b);
    return a ^ b;
#else
    const uint32_t half = (uint32_t)(NROWS * 16) / 2u;
    if (idx < half) {
        uint32_t a = idx, b = idx + half;
        tf2x32(k0, k1, a, b);
        return a;
    } else {
        uint32_t a = idx - half, b = idx;
        tf2x32(k0, k1, a, b);
        return b;
    }
#endif
}

// One group of R rows (R even, R/2 row-pairs). h stored pair-interleaved:
// hw[pair*128 + k] = (h_{2*pair}[k], h_{2*pair+1}[k]) as packed f32x2.
template <int R>
__device__ __forceinline__ void run_group(
    int rowBase, float* __restrict__ sm, u64t* __restrict__ hw,
    int* __restrict__ seqw, int* __restrict__ stw,
    const float4* __restrict__ Wx4, float* __restrict__ out,
    int lane, int g, int tk,
    const u64t* __restrict__ ivd,    // 4: dup(xw0+b) per col (t==0 init)
    float4 bvecv, u64t hinit0, u64t hinit1, u64t hinit2, u64t hinit3,
    float bpt)
{
    constexpr int NP = R / 2;     // row pairs
    constexpr int PH = R / 4;     // pairs per half-warp
    constexpr int SS = R / 2;     // scalar sampler streams per half
    const float NEG_INF = __int_as_float(0xff800000);
    const uint32_t* keys = (const uint32_t*)(sm + SM_KEY);

    // ---- init group ----
#pragma unroll
    for (int p = 0; p < NP; p++) {
        u64t* pw = hw + p * 128 + lane * 4;
        ulonglong2 i0; i0.x = hinit0; i0.y = hinit1;
        ulonglong2 i1; i1.x = hinit2; i1.y = hinit3;
        *(ulonglong2*)(pw)     = i0;
        *(ulonglong2*)(pw + 2) = i1;
    }
    if (lane < R) {
        int* st = stw + lane * 8;
        st[0] = 1; st[1] = 0; st[2] = 1; st[3] = 0; st[4] = 1; st[5] = -1; st[6] = -1;
        out[OFF_MASK + (size_t)(rowBase + lane) * 13] = 1.0f;
    }
    __syncwarp();

    for (int t = 0; t < TSTEPS; t++) {
        const uint32_t k0 = keys[2 * t];
        const uint32_t k1 = keys[2 * t + 1];

        // ---- acc2 init = pack(x@Wx + b) per pair ----
        u64t acc2[NP][4];
        if (t == 0) {
#pragma unroll
            for (int p = 0; p < NP; p++) {
                acc2[p][0] = ivd[0]; acc2[p][1] = ivd[1];
                acc2[p][2] = ivd[2]; acc2[p][3] = ivd[3];
            }
        } else {
#pragma unroll
            for (int p = 0; p < NP; p++) {
                int p0a = stw[(2 * p) * 8 + 5],     p1a = stw[(2 * p) * 8 + 6];
                int p0b = stw[(2 * p + 1) * 8 + 5], p1b = stw[(2 * p + 1) * 8 + 6];
                float4 a0 = make_float4(0.f, 0.f, 0.f, 0.f), c0 = a0, a1 = a0, c1 = a0;
                if (p0a >= 0) a0 = __ldg(Wx4 + p0a * 32 + lane);
                if (p1a >= 0) c0 = __ldg(Wx4 + (16 + p1a) * 32 + lane);
                if (p0b >= 0) a1 = __ldg(Wx4 + p0b * 32 + lane);
                if (p1b >= 0) c1 = __ldg(Wx4 + (16 + p1b) * 32 + lane);
                acc2[p][0] = pk2(a0.x + c0.x + bvecv.x, a1.x + c1.x + bvecv.x);
                acc2[p][1] = pk2(a0.y + c0.y + bvecv.y, a1.y + c1.y + bvecv.y);
                acc2[p][2] = pk2(a0.z + c0.z + bvecv.z, a1.z + c1.z + bvecv.z);
                acc2[p][3] = pk2(a0.w + c0.w + bvecv.w, a1.w + c1.w + bvecv.w);
            }
        }

        // ---- h @ Wh with packed FFMA2: NP pairs, 4 output cols per lane ----
        {
            const float4* Wh4 = (const float4*)sm;  // SM_WH == 0
#pragma unroll 1
            for (int k4 = 0; k4 < 32; k4++) {
                u64t hk[NP][4];
#pragma unroll
                for (int p = 0; p < NP; p++) {
                    // uniform-address 16B broadcast loads
                    ulonglong2 hA = *(const ulonglong2*)(hw + p * 128 + 4 * k4);
                    ulonglong2 hB = *(const ulonglong2*)(hw + p * 128 + 4 * k4 + 2);
                    hk[p][0] = hA.x; hk[p][1] = hA.y;
                    hk[p][2] = hB.x; hk[p][3] = hB.y;
                }
#pragma unroll
                for (int kk = 0; kk < 4; kk++) {
                    float4 w = Wh4[(k4 * 4 + kk) * 32 + lane];
                    u64t wd0 = pkdup(w.x), wd1 = pkdup(w.y);
                    u64t wd2 = pkdup(w.z), wd3 = pkdup(w.w);
#pragma unroll
                    for (int p = 0; p < NP; p++) {
                        acc2[p][0] = fma2(hk[p][kk], wd0, acc2[p][0]);
                        acc2[p][1] = fma2(hk[p][kk], wd1, acc2[p][1]);
                        acc2[p][2] = fma2(hk[p][kk], wd2, acc2[p][2]);
                        acc2[p][3] = fma2(hk[p][kk], wd3, acc2[p][3]);
                    }
                }
            }
            __syncwarp();
            // h_new = tanh(acc) ; store back pair-interleaved (vectorized)
#pragma unroll
            for (int p = 0; p < NP; p++) {
                u64t* pw = hw + p * 128 + lane * 4;
                float l0, h0, l1, h1, l2, h2, l3, h3;
                upk2(acc2[p][0], l0, h0);
                upk2(acc2[p][1], l1, h1);
                upk2(acc2[p][2], l2, h2);
                upk2(acc2[p][3], l3, h3);
                ulonglong2 s0, s1;
                s0.x = pk2(tanhf(l0), tanhf(h0));
                s0.y = pk2(tanhf(l1), tanhf(h1));
                s1.x = pk2(tanhf(l2), tanhf(h2));
                s1.y = pk2(tanhf(l3), tanhf(h3));
                *(ulonglong2*)(pw)     = s0;
                *(ulonglong2*)(pw + 2) = s1;
            }
            __syncwarp();
        }

        // ---- logits: lane = token tk; PH pairs for this half ----
        float lg[SS];
        {
            u64t accl2[PH];
#pragma unroll
            for (int q = 0; q < PH; q++) accl2[q] = 0ull;
            const float4* WpT4 = (const float4*)(sm + SM_WPT);
#pragma unroll 4
            for (int k4 = 0; k4 < 32; k4++) {
                float4 wp = WpT4[tk * 33 + k4];
                u64t wd0 = pkdup(wp.x), wd1 = pkdup(wp.y);
                u64t wd2 = pkdup(wp.z), wd3 = pkdup(wp.w);
#pragma unroll
                for (int q = 0; q < PH; q++) {
                    const u64t* ph = hw + (g + 2 * q) * 128 + 4 * k4;
                    ulonglong2 hA = *(const ulonglong2*)(ph);
                    ulonglong2 hB = *(const ulonglong2*)(ph + 2);
                    accl2[q] = fma2(hA.x, wd0, accl2[q]);
                    accl2[q] = fma2(hA.y, wd1, accl2[q]);
                    accl2[q] = fma2(hB.x, wd2, accl2[q]);
                    accl2[q] = fma2(hB.y, wd3, accl2[q]);
                }
            }
#pragma unroll
            for (int q = 0; q < PH; q++) {
                float lo, hi;
                upk2(accl2[q], lo, hi);
                lg[2 * q]     = lo + bpt;
                lg[2 * q + 1] = hi + bpt;
            }
        }

        // stream s' -> row r = 2*(g + 2*(s'>>1)) + (s'&1)
        int rmap[SS];
#pragma unroll
        for (int s = 0; s < SS; s++) rmap[s] = 2 * (g + 2 * (s >> 1)) + (s & 1);

        // ---- constraints (PRE-update state) ----
        bool ok[SS];
#pragma unroll
        for (int s = 0; s < SS; s++) {
            int r = rmap[s];
            int cnt = stw[r * 8 + 0], ln = stw[r * 8 + 1], hv = stw[r * 8 + 3];
            int cl = cnt + ln;
            bool o = true;
            if (tk >= 8 && cl < 2) o = false;
            if (tk <  8 && cl > TSTEPS - 2) o = false;
            if (tk == 8 && cnt == 1 && hv == 0) o = false;
            ok[s] = o;
        }

        // ---- exact two-stage softmax + mask + renorm (16-lane reductions) ----
        float mx[SS];
#pragma unroll
        for (int s = 0; s < SS; s++) mx[s] = lg[s];
#pragma unroll
        for (int d = 1; d < 16; d <<= 1)
#pragma unroll
            for (int s = 0; s < SS; s++)
                mx[s] = fmaxf(mx[s], __shfl_xor_sync(0xffffffffu, mx[s], d));
        float ex[SS], z[SS];
#pragma unroll
        for (int s = 0; s < SS; s++) { ex[s] = expf(lg[s] - mx[s]); z[s] = ex[s]; }
#pragma unroll
        for (int d = 1; d < 16; d <<= 1)
#pragma unroll
            for (int s = 0; s < SS; s++)
                z[s] += __shfl_xor_sync(0xffffffffu, z[s], d);
        float pm[SS], ssum[SS];
#pragma unroll
        for (int s = 0; s < SS; s++) { pm[s] = ok[s] ? (ex[s] / z[s]) : 0.0f; ssum[s] = pm[s]; }
#pragma unroll
        for (int d = 1; d < 16; d <<= 1)
#pragma unroll
            for (int s = 0; s < SS; s++)
                ssum[s] += __shfl_xor_sync(0xffffffffu, ssum[s], d);
        float p[SS], logp[SS];
        bool pos[SS];
#pragma unroll
        for (int s = 0; s < SS; s++) {
            p[s] = pm[s] / ssum[s];
            pos[s] = p[s] > 0.0f;
            logp[s] = pos[s] ? logf(p[s]) : NEG_INF;
        }

        // ---- gumbel (exact threefry bits) + argmax ----
        float bs[SS];
        int bi[SS];
#pragma unroll
        for (int s = 0; s < SS; s++) {
            uint32_t idx = ((uint32_t)(rowBase + rmap[s])) * 16u + (uint32_t)tk;
            uint32_t bts = gbits(k0, k1, idx);
            float f = __uint_as_float((bts >> 9) | 0x3f800000u) - 1.0f;
            float u = (f == 0.0f) ? 1.17549435e-38f : f;
            float gu = -logf(-logf(u));
            bs[s] = pos[s] ? (logp[s] + gu) : NEG_INF;
            bi[s] = tk;
        }
#pragma unroll
        for (int d = 1; d < 16; d <<= 1) {
#pragma unroll
            for (int s = 0; s < SS; s++) {
                float os = __shfl_xor_sync(0xffffffffu, bs[s], d);
                int   oi = __shfl_xor_sync(0xffffffffu, bi[s], d);
                if (os > bs[s] || (os == bs[s] && oi < bi[s])) { bs[s] = os; bi[s] = oi; }
            }
        }

        // ---- entropy ----
        float et[SS];
#pragma unroll
        for (int s = 0; s < SS; s++) et[s] = pos[s] ? p[s] * logp[s] : 0.0f;
#pragma unroll
        for (int d = 1; d < 16; d <<= 1)
#pragma unroll
            for (int s = 0; s < SS; s++)
                et[s] += __shfl_xor_sync(0xffffffffu, et[s], d);

        // ---- logp at sampled token ----
        float lp[SS];
#pragma unroll
        for (int s = 0; s < SS; s++)
            lp[s] = __shfl_sync(0xffffffffu, logp[s], (lane & 16) + bi[s]);

        // ---- writer lanes: token/state/outputs ----
        if (tk == 0) {
#pragma unroll
            for (int s = 0; s < SS; s++) {
                int r   = rmap[s];
                int tok = bi[s];
                int* st = stw + r * 8;
                int row = rowBase + r;

                seqw[r * 12 + t] = tok;
                int ar  = (tok < 4) ? 2 : ((tok < 8) ? 1 : 0);
                int cnt = st[0] - 1 + ar;
                int ln  = st[1] + 1;
                int act = (cnt > 0) && st[2];
                st[0] = cnt; st[1] = ln; st[2] = act;
                st[3] = st[3] | (tok >= 9);
                st[4] += act;

                out[(size_t)row * 12 + t]                = (float)tok;
                out[OFF_ENT + (size_t)row * 12 + t]      = -et[s];
                out[OFF_LP  + (size_t)row * 12 + t]      = lp[s];
                out[OFF_MASK + (size_t)row * 13 + 1 + t] = act ? 1.0f : 0.0f;
            }
        }
        __syncwarp();

        // ---- parent/sibling scan, parallel across lanes 0..R-1 ----
        if (lane < R) {
            int r = lane;
            int tok = seqw[r * 12 + t];
            int ps0, ps1;
            if (tok < 8) {
                ps0 = tok; ps1 = -1;
            } else {
                ps0 = -1; ps1 = -1;
                int c = 0;
                bool found = false;
                for (int i = t; i >= 0; i--) {
                    int tk2 = seqw[r * 12 + i];
                    int a2 = (tk2 < 4) ? 2 : ((tk2 < 8) ? 1 : 0);
                    c += a2 - 1;
                    if (!found && c == 0) {
                        ps0 = tk2;
                        ps1 = (i + 1 < TSTEPS) ? seqw[r * 12 + i + 1] : -1;
                        found = true;
                    }
                }
            }
            stw[r * 8 + 5] = ps0;
            stw[r * 8 + 6] = ps1;
        }
        __syncwarp();
    }

    // ---- finalize group ----
    if (lane < R) {
        out[OFF_CNT + rowBase + lane] = (float)stw[lane * 8 + 0];
        out[OFF_LEN + rowBase + lane] = (float)stw[lane * 8 + 4];
    }
    __syncwarp();
}

__global__ void __launch_bounds__(THREADS, 2)
eq_sampler(const float* __restrict__ in0, const float* __restrict__ h0,
           const float* __restrict__ Wx, const float* __restrict__ Wh,
           const float* __restrict__ b,  const float* __restrict__ Wp,
           const float* __restrict__ bp, float* __restrict__ out) {
    extern __shared__ float sm[];
    int* smi = (int*)sm;
    const int tid = threadIdx.x;

    for (int i = tid; i < 16384; i += THREADS) sm[SM_WH + i] = Wh[i];
    // transposed, padded Wp: WpT[tok][k], stride 132
    for (int i = tid; i < 2048; i += THREADS) {
        int tok = i >> 7, k = i & 127;
        sm[SM_WPT + tok * 132 + k] = Wp[k * 16 + tok];
    }
    if (tid < 128) sm[SM_B  + tid] = b[tid];
    if (tid < 16)  sm[SM_BP + tid] = bp[tid];
    if (tid < 128) sm[SM_H0 + tid] = h0[tid];

    if (tid == 0) {
        uint32_t* kp = (uint32_t*)(sm + SM_KEY);
#if JAX_PARTITIONABLE
        for (int t = 0; t < TSTEPS; t++) {
            uint32_t a = 0u, bb = (uint32_t)t;
            tf2x32(0u, 42u, a, bb);
            kp[2 * t] = a; kp[2 * t + 1] = bb;
        }
#else
        uint32_t ov[24];
        for (int j = 0; j < 12; j++) {
            uint32_t a = (uint32_t)j, bb = (uint32_t)(j + 12);
            tf2x32(0u, 42u, a, bb);
            ov[j] = a; ov[12 + j] = bb;
        }
        for (int t = 0; t < TSTEPS; t++) { kp[2 * t] = ov[2 * t]; kp[2 * t + 1] = ov[2 * t + 1]; }
#endif
    }
    __syncthreads();

    const int wid  = tid >> 5;
    const int lane = tid & 31;
    const int g    = lane >> 4;
    const int tk   = lane & 15;

    u64t* hw  = (u64t*)(sm + SM_HS) + wid * 512;        // 4 pairs x 128 packed f32x2
    int* seqw = smi + SM_SEQ + wid * 96;                // 8 rows x 12
    int* stw  = smi + SM_ST  + wid * 64;                // 8 rows x 8

    // t=0 input projection (identical for all rows) from global
    float4 xw0v;
    {
        float s0 = 0.f, s1 = 0.f, s2 = 0.f, s3 = 0.f;
#pragma unroll
        for (int k = 0; k < 32; k++) {
            float iv = __ldg(in0 + k);
            const float* wr = Wx + k * 128 + lane * 4;
            s0 = fmaf(iv, __ldg(wr + 0), s0);
            s1 = fmaf(iv, __ldg(wr + 1), s1);
            s2 = fmaf(iv, __ldg(wr + 2), s2);
            s3 = fmaf(iv, __ldg(wr + 3), s3);
        }
        xw0v = make_float4(s0, s1, s2, s3);
    }
    const float4 bvecv = ((const float4*)(sm + SM_B))[lane];
    const float4 hinit = ((const float4*)(sm + SM_H0))[lane];
    const float  bpt   = sm[SM_BP + tk];
    const float4* Wx4  = (const float4*)Wx;

    u64t ivd[4];
    ivd[0] = pkdup(xw0v.x + bvecv.x);
    ivd[1] = pkdup(xw0v.y + bvecv.y);
    ivd[2] = pkdup(xw0v.z + bvecv.z);
    ivd[3] = pkdup(xw0v.w + bvecv.w);
    const u64t hi0 = pkdup(hinit.x), hi1 = pkdup(hinit.y);
    const u64t hi2 = pkdup(hinit.z), hi3 = pkdup(hinit.w);

    const int totalWarps = gridDim.x * WPB;
    const int gwid = blockIdx.x * WPB + wid;

    // main phase: R=8 groups, exactly (full8 / totalWarps) per warp
    const int full8 = NROWS / 8;
    const int base8 = (full8 / totalWarps) * totalWarps;
    for (int grp = gwid; grp < base8; grp += totalWarps)
        run_group<8>(grp * 8, sm, hw, seqw, stw, Wx4, out,
                     lane, g, tk, ivd, bvecv, hi0, hi1, hi2, hi3, bpt);

    // tail phase: remaining rows as R=4 groups
    const int tailRowBase = base8 * 8;
    const int tail4 = (NROWS - tailRowBase) / 4;
    for (int grp = gwid; grp < tail4; grp += totalWarps)
        run_group<4>(tailRowBase + grp * 4, sm, hw, seqw, stw, Wx4, out,
                     lane, g, tk, ivd, bvecv, hi0, hi1, hi2, hi3, bpt);
}

extern "C" void kernel_launch(void* const* d_in, const int* in_sizes, int n_in,
                              void* d_out, int out_size) {
    int base = (in_sizes[0] == 1) ? 1 : 0;
    const float* in0 = (const float*)d_in[base + 0];
    const float* h0  = (const float*)d_in[base + 1];
    const float* Wx  = (const float*)d_in[base + 2];
    const float* Wh  = (const float*)d_in[base + 3];
    const float* b   = (const float*)d_in[base + 4];
    const float* Wp  = (const float*)d_in[base + 5];
    const float* bp  = (const float*)d_in[base + 6];

    size_t smem = (size_t)SM_TOTF * sizeof(float);
    cudaFuncSetAttribute(eq_sampler, cudaFuncAttributeMaxDynamicSharedMemorySize, (int)smem);
    eq_sampler<<<NBLOCKS, THREADS, smem>>>(in0, h0, Wx, Wh, b, Wp, bp, (float*)d_out);
}